// round 11
// baseline (speedup 1.0000x reference)
#include <cuda_runtime.h>

#define BSZ 2
#define SEQ 4096
#define NH 16
#define DP 64
#define DN 128
#define CS 64
#define NC 64
#define NPAIR 32
#define TPB 256
#define PTPB 512
#define P2TPB 512

__device__ float g_CB[(size_t)NC * NPAIR * CS * CS];
__device__ float g_M[(size_t)NC * NPAIR * CS * CS];
__device__ float g_h[(size_t)NC * NPAIR * DN * DP];
__device__ float g_ds[NC];
__device__ float g_err[NC][NPAIR];
__device__ unsigned g_arrive;

__device__ __forceinline__ void cpa16(float* s, const float* g) {
    unsigned a = (unsigned)__cvta_generic_to_shared(s);
    asm volatile("cp.async.cg.shared.global [%0], [%1], 16;\n" :: "r"(a), "l"(g));
}
__device__ __forceinline__ void cpa4(float* s, const float* g) {
    unsigned a = (unsigned)__cvta_generic_to_shared(s);
    asm volatile("cp.async.ca.shared.global [%0], [%1], 4;\n" :: "r"(a), "l"(g));
}
#define CP_COMMIT() asm volatile("cp.async.commit_group;\n" ::: "memory")
#define CP_WAIT1()  asm volatile("cp.async.wait_group 1;\n" ::: "memory")
#define CP_WAIT0()  asm volatile("cp.async.wait_group 0;\n" ::: "memory")

__device__ __forceinline__ float dot4(float4 a, float4 b) {
    return fmaf(a.x, b.x, fmaf(a.y, b.y, fmaf(a.z, b.z, a.w * b.w)));
}

__device__ __forceinline__ void scan_warp0(int lane, const float* sA, float* sP) {
    float v0 = sA[2 * lane], v1 = sA[2 * lane + 1];
    float s = v0 + v1;
#pragma unroll
    for (int o = 1; o < 32; o <<= 1) {
        float t = __shfl_up_sync(0xffffffffu, s, o);
        if (lane >= o) s += t;
    }
    sP[2 * lane] = s - v1;
    sP[2 * lane + 1] = s;
}

__device__ __forceinline__ void gate_warp0(int c, int lane, float* sEma,
                                           const float* sAB, const float* sBet, float* sDS) {
    int hh = lane & 15;
    float e = __ldcg(&g_err[c - 1][lane]) * (1.f / 8192.f);
    float e0 = __shfl_sync(0xffffffffu, e, hh);
    float e1 = __shfl_sync(0xffffffffu, e, hh + 16);
    float emn = 0.99f * sEma[hh] + 0.01f * (0.5f * (e0 + e1));
    __syncwarp();
    if (lane < 16) sEma[hh] = emn;
    __syncwarp();
    float nrm = e / (emn + 1e-6f);
    float boost = fmaxf(tanhf(sBet[hh] * nrm), 0.f);
    float ab = sAB[hh];
    float alpha = fminf(fmaxf(ab + (1.f - ab) * boost, 0.01f), 0.999f);
    float oma = 1.f - alpha;
#pragma unroll
    for (int o = 16; o; o >>= 1) oma += __shfl_xor_sync(0xffffffffu, oma, o);
    if (lane == 0) sDS[0] = oma * (1.f / 32.f);
}

__device__ __forceinline__ void wait_arrive(unsigned target) {
    unsigned v;
    do {
        asm volatile("ld.acquire.gpu.global.u32 %0, [%1];" : "=r"(v) : "l"(&g_arrive) : "memory");
    } while (v < target);
}

// ============================================================================
// PREP: CB = C·B^T (lower needed; upper cols<32 incidental) and M = (BB^T)∘(XX^T)
// warp-strip mapping: warp w -> rows 4w..4w+3 (broadcast), lanes -> cols l, l+32
// ============================================================================
__global__ void __launch_bounds__(PTPB, 1) prep_kernel(const float* __restrict__ Cm,
                                                       const float* __restrict__ Bm,
                                                       const float* __restrict__ Xm) {
    if (blockIdx.x == 0 && threadIdx.x == 0) g_arrive = 0u;
    extern __shared__ float smem[];
    float* sC = smem;                 // [64][128] XOR-swizzled (32 groups)
    float* sB = smem + 8192;          // [64][128]
    float* sX = smem + 16384;         // [64][64]  XOR-swizzled (16 groups)
    const int tid = threadIdx.x;
    const int c = blockIdx.x >> 5, pair = blockIdx.x & 31;
    const int b = pair >> 4, h = pair & 15;
    const size_t rb = ((size_t)((size_t)b * SEQ + (size_t)c * CS) * NH + h);
    const float* Cg = Cm + rb * DN;
    const float* Bg = Bm + rb * DN;
    const float* Xg = Xm + rb * DP;
    for (int idx = tid; idx < 2048; idx += PTPB) {
        int i = idx >> 5, g = idx & 31;
        cpa16(sC + i * 128 + ((g ^ (i & 31)) << 2), Cg + (size_t)i * 2048 + g * 4);
        cpa16(sB + i * 128 + ((g ^ (i & 31)) << 2), Bg + (size_t)i * 2048 + g * 4);
    }
    for (int idx = tid; idx < 1024; idx += PTPB) {
        int j = idx >> 4, g = idx & 15;
        cpa16(sX + j * 64 + ((g ^ (j & 15)) << 2), Xg + (size_t)j * 1024 + g * 4);
    }
    CP_COMMIT(); CP_WAIT0();
    __syncthreads();

    const int w = tid >> 5, l = tid & 31;
    const int r0 = w * 4;
    const int j1 = l, j2 = l + 32;
    const bool hi = (w >= 8);
    const float4* sC4 = (const float4*)sC;
    const float4* sB4 = (const float4*)sB;
    const float4* sX4 = (const float4*)sX;

    float cb1[4] = {}, cb2[4] = {}, bb1[4] = {}, bb2[4] = {};
#pragma unroll 4
    for (int k4 = 0; k4 < 32; k4++) {
        float4 bj1 = sB4[j1 * 32 + (k4 ^ j1)];
        float4 bj2 = hi ? sB4[j2 * 32 + (k4 ^ (j2 & 31))] : make_float4(0.f, 0.f, 0.f, 0.f);
#pragma unroll
        for (int a = 0; a < 4; a++) {
            int rr = r0 + a;
            float4 cr = sC4[rr * 32 + (k4 ^ (rr & 31))];
            float4 bi = sB4[rr * 32 + (k4 ^ (rr & 31))];
            cb1[a] += dot4(cr, bj1);
            bb1[a] += dot4(bi, bj1);
            if (hi) {
                cb2[a] += dot4(cr, bj2);
                bb2[a] += dot4(bi, bj2);
            }
        }
    }
    {
        float* cbo = g_CB + (size_t)(c * NPAIR + pair) * CS * CS;
#pragma unroll
        for (int a = 0; a < 4; a++) {
            cbo[(r0 + a) * CS + j1] = cb1[a];
            if (hi) cbo[(r0 + a) * CS + j2] = cb2[a];
        }
    }
    float xx1[4] = {}, xx2[4] = {};
#pragma unroll 4
    for (int g = 0; g < 16; g++) {
        float4 xj1 = sX4[j1 * 16 + (g ^ (j1 & 15))];
        float4 xj2 = hi ? sX4[j2 * 16 + (g ^ (j2 & 15))] : make_float4(0.f, 0.f, 0.f, 0.f);
#pragma unroll
        for (int a = 0; a < 4; a++) {
            int rr = r0 + a;
            float4 xi = sX4[rr * 16 + (g ^ (rr & 15))];
            xx1[a] += dot4(xi, xj1);
            if (hi) xx2[a] += dot4(xi, xj2);
        }
    }
    {
        float* mo = g_M + (size_t)(c * NPAIR + pair) * CS * CS;
#pragma unroll
        for (int a = 0; a < 4; a++) {
            int rr = r0 + a;
            float m1 = bb1[a] * xx1[a];
            mo[rr * CS + j1] = m1;
            if (hi) {
                mo[j1 * CS + rr] = m1;             // mirror fills upper-right quadrant
                mo[rr * CS + j2] = bb2[a] * xx2[a];
            }
        }
    }
}

// ============================================================================
// PASS 1: 32 chain CTAs (gate + w^T M w, double-accum) + 128 worker CTAs (h rec.)
// ============================================================================
// header floats: sP 0..63 | sEma 64 | sAB 80 | sBet 96 | sDS 112 | sRedD @120 (8 dbl)
//                sW 136..199 | (pad) | sXw 208..1231
#define HDR 1232
#define CM_M 0
#define CM_A 4352          // M [64][68]
#define CBUF 4416
#define WB_B 0             // B [64][128]
#define WB_X 8192          // X slice [64][16]
#define WB_A 9216
#define WBUF 9280
#define SMEM1_FLOATS (HDR + 2 * WBUF)   // 19792 floats = 79168 B

__global__ void __launch_bounds__(TPB, 2) pass1_kernel(
    const float* __restrict__ X, const float* __restrict__ A,
    const float* __restrict__ Bm,
    const float* __restrict__ la, const float* __restrict__ lb,
    const float* __restrict__ ema0) {
    extern __shared__ float smem[];
    const int tid = threadIdx.x, lane = tid & 31, wid = tid >> 5;
    float* sP = smem; float* sEma = smem + 64; float* sAB = smem + 80;
    float* sBet = smem + 96; float* sDS = smem + 112;
    double* sRedD = (double*)(smem + 120);
    float* sW = smem + 136; float* sXw = smem + 208;
    if (tid < NH) {
        sAB[tid] = 1.f - exp2f(fminf(fmaxf(la[tid], -3.32f), -0.015f));
        sBet[tid] = exp2f(fminf(fmaxf(lb[tid], -2.f), 2.f));
        sEma[tid] = ema0[tid];
    }

    if (blockIdx.x < 32) {  // ======== CHAIN ========
        const int pair = blockIdx.x, b = pair >> 4, h = pair & 15;
        {
            const float* Mg = g_M + (size_t)pair * CS * CS;
            float* buf = smem + HDR;
            for (int i = tid; i < 1024; i += TPB)
                cpa16(buf + CM_M + (i >> 4) * 68 + (i & 15) * 4, Mg + (i >> 4) * 64 + (i & 15) * 4);
            if (tid < CS) cpa4(buf + CM_A + tid, A + ((size_t)b * SEQ + tid) * NH + h);
        }
        CP_COMMIT();
        __syncthreads();
        for (int c = 0; c < NC; ++c) {
            float* cur = smem + HDR + ((c & 1) ? CBUF : 0);
            float* nxt = smem + HDR + ((c & 1) ? 0 : CBUF);
            if (c + 1 < NC) {
                const float* Mg = g_M + (size_t)((c + 1) * NPAIR + pair) * CS * CS;
                for (int i = tid; i < 1024; i += TPB)
                    cpa16(nxt + CM_M + (i >> 4) * 68 + (i & 15) * 4, Mg + (i >> 4) * 64 + (i & 15) * 4);
                if (tid < CS)
                    cpa4(nxt + CM_A + tid, A + ((size_t)b * SEQ + (c + 1) * CS + tid) * NH + h);
                CP_COMMIT(); CP_WAIT1();
            } else CP_WAIT0();
            __syncthreads();
            if (wid == 0) scan_warp0(lane, cur + CM_A, sP);
            if (c > 0) {
                if (tid == 0) wait_arrive(32u * (unsigned)c);
                __syncthreads();
                if (wid == 0) gate_warp0(c, lane, sEma, sAB, sBet, sDS);
            } else if (tid == 0) sDS[0] = 1.f;
            __syncthreads();
            const float dsv = sDS[0], pT = sP[CS - 1];
            if (tid < CS) sW[tid] = __expf(dsv * (pT - sP[tid]));
            if (pair == 0 && tid == 64) g_ds[c] = dsv;
            __syncthreads();
            {   // err = w^T M w  (double accumulation)
                int r = tid & 63, seg = tid >> 6;
                const float* mrow = cur + CM_M + r * 68 + seg * 16;
                const float* ws = sW + seg * 16;
                double p = 0.0;
#pragma unroll
                for (int i = 0; i < 4; i++) {
                    float4 m = *(const float4*)(mrow + i * 4);
                    float4 wv = *(const float4*)(ws + i * 4);
                    p += (double)m.x * wv.x + (double)m.y * wv.y
                       + (double)m.z * wv.z + (double)m.w * wv.w;
                }
                p *= (double)sW[r];
#pragma unroll
                for (int o = 16; o; o >>= 1) p += __shfl_xor_sync(0xffffffffu, p, o);
                if (lane == 0) sRedD[wid] = p;
            }
            __syncthreads();
            if (tid == 0) {
                double tot = 0.0;
#pragma unroll
                for (int w = 0; w < 8; w++) tot += sRedD[w];
                float totf = (float)tot;
                asm volatile("st.global.cg.f32 [%0], %1;" :: "l"(&g_err[c][pair]), "f"(totf) : "memory");
                unsigned d_;
                asm volatile("atom.release.gpu.global.add.u32 %0, [%1], 1;"
                             : "=r"(d_) : "l"(&g_arrive) : "memory");
            }
        }
    } else {  // ======== WORKER ========
        const int idx = blockIdx.x - 32;
        const int pair = idx >> 2, slice = idx & 3;
        const int b = pair >> 4, h = pair & 15;
        const int p0 = slice * 16;
        const int n0 = tid & 127, ph = (tid >> 7) * 8;
        float4 hA = make_float4(0.f, 0.f, 0.f, 0.f);
        float4 hB = make_float4(0.f, 0.f, 0.f, 0.f);
        {
            float* buf = smem + HDR;
            const float* Bg = Bm + ((size_t)b * SEQ * NH + h) * DN;
            const float* Xg = X + ((size_t)b * SEQ * NH + h) * DP + p0;
            for (int i2 = tid; i2 < 2048; i2 += TPB)
                cpa16(buf + WB_B + (i2 >> 5) * DN + (i2 & 31) * 4, Bg + (size_t)(i2 >> 5) * 2048 + (i2 & 31) * 4);
            if (tid < 256) cpa16(buf + WB_X + (tid >> 2) * 16 + (tid & 3) * 4,
                                 Xg + (size_t)(tid >> 2) * 1024 + (tid & 3) * 4);
            if (tid < CS) cpa4(buf + WB_A + tid, A + ((size_t)b * SEQ + tid) * NH + h);
        }
        CP_COMMIT();
        __syncthreads();
        for (int c = 0; c < NC; ++c) {
            float* cur = smem + HDR + ((c & 1) ? WBUF : 0);
            float* nxt = smem + HDR + ((c & 1) ? 0 : WBUF);
            if (c + 1 < NC) {
                size_t rb = ((size_t)b * SEQ + (c + 1) * CS) * NH + h;
                const float* Bg = Bm + rb * DN;
                const float* Xg = X + rb * DP + p0;
                for (int i2 = tid; i2 < 2048; i2 += TPB)
                    cpa16(nxt + WB_B + (i2 >> 5) * DN + (i2 & 31) * 4, Bg + (size_t)(i2 >> 5) * 2048 + (i2 & 31) * 4);
                if (tid < 256) cpa16(nxt + WB_X + (tid >> 2) * 16 + (tid & 3) * 4,
                                     Xg + (size_t)(tid >> 2) * 1024 + (tid & 3) * 4);
                if (tid < CS) cpa4(nxt + WB_A + tid, A + ((size_t)b * SEQ + (c + 1) * CS + tid) * NH + h);
                CP_COMMIT(); CP_WAIT1();
            } else CP_WAIT0();
            __syncthreads();
            if (wid == 0) scan_warp0(lane, cur + WB_A, sP);
            if (c > 0) {
                if (tid == 0) wait_arrive(32u * (unsigned)c);
                __syncthreads();
                if (wid == 0) gate_warp0(c, lane, sEma, sAB, sBet, sDS);
            } else if (tid == 0) sDS[0] = 1.f;
            __syncthreads();
            const float dsv = sDS[0], pT = sP[CS - 1];
#pragma unroll
            for (int k = tid; k < CS * 16; k += TPB)
                sXw[k] = __expf(dsv * (pT - sP[k >> 4])) * cur[WB_X + k];
            __syncthreads();
            {
                const float* xw = sXw + ph;
                float4 c1 = make_float4(0.f, 0.f, 0.f, 0.f);
                float4 c2 = make_float4(0.f, 0.f, 0.f, 0.f);
#pragma unroll 8
                for (int t = 0; t < CS; t++) {
                    float b1 = cur[WB_B + t * DN + n0];
                    float4 w0 = *(const float4*)(xw + t * 16);
                    float4 w1 = *(const float4*)(xw + t * 16 + 4);
                    c1.x = fmaf(b1, w0.x, c1.x); c1.y = fmaf(b1, w0.y, c1.y);
                    c1.z = fmaf(b1, w0.z, c1.z); c1.w = fmaf(b1, w0.w, c1.w);
                    c2.x = fmaf(b1, w1.x, c2.x); c2.y = fmaf(b1, w1.y, c2.y);
                    c2.z = fmaf(b1, w1.z, c2.z); c2.w = fmaf(b1, w1.w, c2.w);
                }
                float dt = __expf(dsv * pT);
                hA.x = fmaf(dt, hA.x, c1.x); hA.y = fmaf(dt, hA.y, c1.y);
                hA.z = fmaf(dt, hA.z, c1.z); hA.w = fmaf(dt, hA.w, c1.w);
                hB.x = fmaf(dt, hB.x, c2.x); hB.y = fmaf(dt, hB.y, c2.y);
                hB.z = fmaf(dt, hB.z, c2.z); hB.w = fmaf(dt, hB.w, c2.w);
            }
            if (c + 1 < NC) {
                float* gh = g_h + ((size_t)(c + 1) * NPAIR + pair) * (DN * DP)
                            + (size_t)(p0 + ph) * DN + n0;
                gh[0 * DN] = hA.x; gh[1 * DN] = hA.y; gh[2 * DN] = hA.z; gh[3 * DN] = hA.w;
                gh[4 * DN] = hB.x; gh[5 * DN] = hB.y; gh[6 * DN] = hB.z; gh[7 * DN] = hB.w;
            }
            __syncthreads();
        }
    }
}

// ---------------- PASS 2 (unchanged structure) ----------------
#define P2_C 0
#define P2_H 8192
#define P2_CB 16384
#define P2_X 20480
#define P2_A 24576
#define P2_P 24640
#define P2_DFS 24704
#define P2_INV 24768
#define SMEM2_FLOATS 24832

__global__ void __launch_bounds__(P2TPB, 2) pass2_kernel(
    const float* __restrict__ X, const float* __restrict__ A,
    const float* __restrict__ Cm, float* __restrict__ Y) {
    extern __shared__ float smem[];
    const int tid = threadIdx.x, lane = tid & 31, wid = tid >> 5;
    const int c = blockIdx.x >> 5, pair = blockIdx.x & 31;
    const int b = pair >> 4, h = pair & 15;
    const int yi = tid & 63, pq = tid >> 6;
    float* sC = smem + P2_C; float* sH = smem + P2_H; float* sCB = smem + P2_CB;
    float* sX = smem + P2_X; float* sP = smem + P2_P;
    float* sDfs = smem + P2_DFS; float* sInv = smem + P2_INV;
    const size_t rowbase = ((size_t)((size_t)b * SEQ + (size_t)c * CS) * NH + h);
    const float* Cg = Cm + rowbase * DN;
    const float* Xg = X + rowbase * DP;
    const float* CBg = g_CB + (size_t)(c * NPAIR + pair) * CS * CS;
    const float* Hg = g_h + ((size_t)c * NPAIR + pair) * (DN * DP);
#pragma unroll
    for (int idx = tid; idx < 2048; idx += P2TPB) {
        int i = idx >> 5, g = idx & 31;
        cpa16(sC + i * DN + ((g ^ (i & 31)) << 2), Cg + (size_t)i * 2048 + g * 4);
    }
    if (c > 0)
#pragma unroll
        for (int idx = tid; idx < 2048; idx += P2TPB) cpa16(sH + idx * 4, Hg + idx * 4);
#pragma unroll
    for (int idx = tid; idx < 1024; idx += P2TPB) {
        int i = idx >> 4, g4 = idx & 15;
        cpa16(sCB + i * CS + ((g4 ^ (i & 15)) << 2), CBg + i * CS + g4 * 4);
    }
#pragma unroll
    for (int idx = tid; idx < 1024; idx += P2TPB) {
        int j = idx >> 4, p4 = idx & 15;
        cpa16(sX + j * DP + p4 * 4, Xg + (size_t)j * 1024 + p4 * 4);
    }
    if (tid < CS) cpa4(smem + P2_A + tid, A + ((size_t)b * SEQ + c * CS + tid) * NH + h);
    CP_COMMIT(); CP_WAIT0();
    __syncthreads();
    if (wid == 0) scan_warp0(lane, smem + P2_A, sP);
    __syncthreads();
    const float dsv = (c == 0) ? 1.f : __ldg(&g_ds[c]);
    if (tid < CS) {
        float a = dsv * sP[tid];
        sDfs[tid] = __expf(a); sInv[tid] = __expf(-a);
    }
    __syncthreads();
#pragma unroll
    for (int idx = tid; idx < CS * DP; idx += P2TPB) sX[idx] *= sInv[idx >> 6];
#pragma unroll
    for (int idx = tid; idx < CS * CS; idx += P2TPB) {
        int i = idx >> 6, j = idx & 63;
        if (j > i) sCB[i * CS + (((j >> 2) ^ (i & 15)) << 2) + (j & 3)] = 0.f;
    }
    __syncthreads();
    float acc[8] = {};
    if (c > 0) {
        const float* crow = sC + yi * DN;
        const int sw = yi & 31;
        const float* hb = sH + pq * 8 * DN;
#pragma unroll 4
        for (int g = 0; g < 32; g++) {
            float4 cv = *(const float4*)(crow + ((g ^ sw) << 2));
#pragma unroll
            for (int e = 0; e < 8; e++) {
                float4 hv = *(const float4*)(hb + e * DN + g * 4);
                acc[e] = fmaf(cv.x, hv.x, acc[e]); acc[e] = fmaf(cv.y, hv.y, acc[e]);
                acc[e] = fmaf(cv.z, hv.z, acc[e]); acc[e] = fmaf(cv.w, hv.w, acc[e]);
            }
        }
    }
    {
        const float* cbrow = sCB + yi * CS;
        const int sw4 = yi & 15;
        const int gmax = (yi < 32) ? 8 : 16;
        for (int g4 = 0; g4 < gmax; g4++) {
            float4 cb = *(const float4*)(cbrow + ((g4 ^ sw4) << 2));
#pragma unroll
            for (int k = 0; k < 4; k++) {
                float cbk = (k == 0) ? cb.x : (k == 1) ? cb.y : (k == 2) ? cb.z : cb.w;
                const float* xr = sX + (g4 * 4 + k) * DP + pq * 8;
                float4 x0 = *(const float4*)(xr);
                float4 x1 = *(const float4*)(xr + 4);
                acc[0] = fmaf(cbk, x0.x, acc[0]); acc[1] = fmaf(cbk, x0.y, acc[1]);
                acc[2] = fmaf(cbk, x0.z, acc[2]); acc[3] = fmaf(cbk, x0.w, acc[3]);
                acc[4] = fmaf(cbk, x1.x, acc[4]); acc[5] = fmaf(cbk, x1.y, acc[5]);
                acc[6] = fmaf(cbk, x1.z, acc[6]); acc[7] = fmaf(cbk, x1.w, acc[7]);
            }
        }
    }
    {
        float d = sDfs[yi];
        float* yo = Y + (rowbase + (size_t)yi * NH) * DP + pq * 8;
        *(float4*)yo = make_float4(acc[0] * d, acc[1] * d, acc[2] * d, acc[3] * d);
        *(float4*)(yo + 4) = make_float4(acc[4] * d, acc[5] * d, acc[6] * d, acc[7] * d);
    }
}

extern "C" void kernel_launch(void* const* d_in, const int* in_sizes, int n_in,
                              void* d_out, int out_size) {
    const float* X = (const float*)d_in[0];
    const float* A = (const float*)d_in[1];
    const float* Bm = (const float*)d_in[2];
    const float* Cm = (const float*)d_in[3];
    const float* la = (const float*)d_in[4];
    const float* lb = (const float*)d_in[5];
    const float* em = (const float*)d_in[6];
    float* Y = (float*)d_out;
    const int prep_smem = (2 * 8192 + 4096) * sizeof(float);   // 81920 B
    const int p1_smem = SMEM1_FLOATS * sizeof(float);
    const int p2_smem = SMEM2_FLOATS * sizeof(float);
    cudaFuncSetAttribute(prep_kernel, cudaFuncAttributeMaxDynamicSharedMemorySize, prep_smem);
    cudaFuncSetAttribute(pass1_kernel, cudaFuncAttributeMaxDynamicSharedMemorySize, p1_smem);
    cudaFuncSetAttribute(pass2_kernel, cudaFuncAttributeMaxDynamicSharedMemorySize, p2_smem);
    prep_kernel<<<NC * NPAIR, PTPB, prep_smem>>>(Cm, Bm, X);
    pass1_kernel<<<160, TPB, p1_smem>>>(X, A, Bm, la, lb, em);
    pass2_kernel<<<NC * NPAIR, P2TPB, p2_smem>>>(X, A, Cm, Y);
}

// round 13
// speedup vs baseline: 1.0010x; 1.0010x over previous
#include <cuda_runtime.h>

#define BSZ 2
#define SEQ 4096
#define NH 16
#define DP 64
#define DN 128
#define CS 64
#define NC 64
#define NPAIR 32
#define TPB 256
#define PTPB 512
#define P2TPB 512

__device__ float g_CB[(size_t)NC * NPAIR * CS * CS];
__device__ float g_M[(size_t)NC * NPAIR * CS * CS];
__device__ float g_h[(size_t)NC * NPAIR * DN * DP];
__device__ float g_ds[NC];
__device__ float g_err[NC][NPAIR];
__device__ unsigned g_arrive;

__device__ __forceinline__ void cpa16(float* s, const float* g) {
    unsigned a = (unsigned)__cvta_generic_to_shared(s);
    asm volatile("cp.async.cg.shared.global [%0], [%1], 16;\n" :: "r"(a), "l"(g));
}
__device__ __forceinline__ void cpa4(float* s, const float* g) {
    unsigned a = (unsigned)__cvta_generic_to_shared(s);
    asm volatile("cp.async.ca.shared.global [%0], [%1], 4;\n" :: "r"(a), "l"(g));
}
#define CP_COMMIT() asm volatile("cp.async.commit_group;\n" ::: "memory")
#define CP_WAIT1()  asm volatile("cp.async.wait_group 1;\n" ::: "memory")
#define CP_WAIT0()  asm volatile("cp.async.wait_group 0;\n" ::: "memory")

__device__ __forceinline__ float dot4(float4 a, float4 b) {
    return fmaf(a.x, b.x, fmaf(a.y, b.y, fmaf(a.z, b.z, a.w * b.w)));
}

__device__ __forceinline__ void scan_warp0(int lane, const float* sA, float* sP) {
    float v0 = sA[2 * lane], v1 = sA[2 * lane + 1];
    float s = v0 + v1;
#pragma unroll
    for (int o = 1; o < 32; o <<= 1) {
        float t = __shfl_up_sync(0xffffffffu, s, o);
        if (lane >= o) s += t;
    }
    sP[2 * lane] = s - v1;
    sP[2 * lane + 1] = s;
}

__device__ __forceinline__ void gate_warp0(int c, int lane, float* sEma,
                                           const float* sAB, const float* sBet, float* sDS) {
    int hh = lane & 15;
    float e = __ldcg(&g_err[c - 1][lane]) * (1.f / 8192.f);
    float e0 = __shfl_sync(0xffffffffu, e, hh);
    float e1 = __shfl_sync(0xffffffffu, e, hh + 16);
    float emn = 0.99f * sEma[hh] + 0.01f * (0.5f * (e0 + e1));
    __syncwarp();
    if (lane < 16) sEma[hh] = emn;
    __syncwarp();
    float nrm = e / (emn + 1e-6f);
    float boost = fmaxf(tanhf(sBet[hh] * nrm), 0.f);
    float ab = sAB[hh];
    float alpha = fminf(fmaxf(ab + (1.f - ab) * boost, 0.01f), 0.999f);
    float oma = 1.f - alpha;
#pragma unroll
    for (int o = 16; o; o >>= 1) oma += __shfl_xor_sync(0xffffffffu, oma, o);
    if (lane == 0) sDS[0] = oma * (1.f / 32.f);
}

__device__ __forceinline__ void wait_arrive(unsigned target) {
    unsigned v;
    do {
        asm volatile("ld.acquire.gpu.global.u32 %0, [%1];" : "=r"(v) : "l"(&g_arrive) : "memory");
    } while (v < target);
}

// ============================================================================
// PREP: CB = C·B^T (lower needed; upper cols<32 incidental) and M = (BB^T)∘(XX^T)
// warp-strip mapping: warp w -> rows 4w..4w+3 (broadcast), lanes -> cols l, l+32
// ============================================================================
__global__ void __launch_bounds__(PTPB, 1) prep_kernel(const float* __restrict__ Cm,
                                                       const float* __restrict__ Bm,
                                                       const float* __restrict__ Xm) {
    if (blockIdx.x == 0 && threadIdx.x == 0) g_arrive = 0u;
    extern __shared__ float smem[];
    float* sC = smem;                 // [64][128] XOR-swizzled (32 groups)
    float* sB = smem + 8192;          // [64][128]
    float* sX = smem + 16384;         // [64][64]  XOR-swizzled (16 groups)
    const int tid = threadIdx.x;
    const int c = blockIdx.x >> 5, pair = blockIdx.x & 31;
    const int b = pair >> 4, h = pair & 15;
    const size_t rb = ((size_t)((size_t)b * SEQ + (size_t)c * CS) * NH + h);
    const float* Cg = Cm + rb * DN;
    const float* Bg = Bm + rb * DN;
    const float* Xg = Xm + rb * DP;
    for (int idx = tid; idx < 2048; idx += PTPB) {
        int i = idx >> 5, g = idx & 31;
        cpa16(sC + i * 128 + ((g ^ (i & 31)) << 2), Cg + (size_t)i * 2048 + g * 4);
        cpa16(sB + i * 128 + ((g ^ (i & 31)) << 2), Bg + (size_t)i * 2048 + g * 4);
    }
    for (int idx = tid; idx < 1024; idx += PTPB) {
        int j = idx >> 4, g = idx & 15;
        cpa16(sX + j * 64 + ((g ^ (j & 15)) << 2), Xg + (size_t)j * 1024 + g * 4);
    }
    CP_COMMIT(); CP_WAIT0();
    __syncthreads();

    const int w = tid >> 5, l = tid & 31;
    const int r0 = w * 4;
    const int j1 = l, j2 = l + 32;
    const bool hi = (w >= 8);
    const float4* sC4 = (const float4*)sC;
    const float4* sB4 = (const float4*)sB;
    const float4* sX4 = (const float4*)sX;

    float cb1[4] = {}, cb2[4] = {}, bb1[4] = {}, bb2[4] = {};
#pragma unroll 4
    for (int k4 = 0; k4 < 32; k4++) {
        float4 bj1 = sB4[j1 * 32 + (k4 ^ j1)];
        float4 bj2 = hi ? sB4[j2 * 32 + (k4 ^ (j2 & 31))] : make_float4(0.f, 0.f, 0.f, 0.f);
#pragma unroll
        for (int a = 0; a < 4; a++) {
            int rr = r0 + a;
            float4 cr = sC4[rr * 32 + (k4 ^ (rr & 31))];
            float4 bi = sB4[rr * 32 + (k4 ^ (rr & 31))];
            cb1[a] += dot4(cr, bj1);
            bb1[a] += dot4(bi, bj1);
            if (hi) {
                cb2[a] += dot4(cr, bj2);
                bb2[a] += dot4(bi, bj2);
            }
        }
    }
    {
        float* cbo = g_CB + (size_t)(c * NPAIR + pair) * CS * CS;
#pragma unroll
        for (int a = 0; a < 4; a++) {
            cbo[(r0 + a) * CS + j1] = cb1[a];
            if (hi) cbo[(r0 + a) * CS + j2] = cb2[a];
        }
    }
    float xx1[4] = {}, xx2[4] = {};
#pragma unroll 4
    for (int g = 0; g < 16; g++) {
        float4 xj1 = sX4[j1 * 16 + (g ^ (j1 & 15))];
        float4 xj2 = hi ? sX4[j2 * 16 + (g ^ (j2 & 15))] : make_float4(0.f, 0.f, 0.f, 0.f);
#pragma unroll
        for (int a = 0; a < 4; a++) {
            int rr = r0 + a;
            float4 xi = sX4[rr * 16 + (g ^ (rr & 15))];
            xx1[a] += dot4(xi, xj1);
            if (hi) xx2[a] += dot4(xi, xj2);
        }
    }
    {
        float* mo = g_M + (size_t)(c * NPAIR + pair) * CS * CS;
#pragma unroll
        for (int a = 0; a < 4; a++) {
            int rr = r0 + a;
            float m1 = bb1[a] * xx1[a];
            mo[rr * CS + j1] = m1;
            if (hi) {
                mo[j1 * CS + rr] = m1;             // mirror fills upper-right quadrant
                mo[rr * CS + j2] = bb2[a] * xx2[a];
            }
        }
    }
}

// ============================================================================
// PASS 1: 32 chain CTAs (gate + w^T M w, double-accum) + 128 worker CTAs (h rec.)
// ============================================================================
// header floats: sP 0..63 | sEma 64 | sAB 80 | sBet 96 | sDS 112 | sRedD @120 (8 dbl)
//                sW 136..199 | (pad) | sXw 208..1231
#define HDR 1232
#define CM_M 0
#define CM_A 4352          // M [64][68]
#define CBUF 4416
#define WB_B 0             // B [64][128]
#define WB_X 8192          // X slice [64][16]
#define WB_A 9216
#define WBUF 9280
#define SMEM1_FLOATS (HDR + 2 * WBUF)   // 19792 floats = 79168 B

__global__ void __launch_bounds__(TPB, 2) pass1_kernel(
    const float* __restrict__ X, const float* __restrict__ A,
    const float* __restrict__ Bm,
    const float* __restrict__ la, const float* __restrict__ lb,
    const float* __restrict__ ema0) {
    extern __shared__ float smem[];
    const int tid = threadIdx.x, lane = tid & 31, wid = tid >> 5;
    float* sP = smem; float* sEma = smem + 64; float* sAB = smem + 80;
    float* sBet = smem + 96; float* sDS = smem + 112;
    double* sRedD = (double*)(smem + 120);
    float* sW = smem + 136; float* sXw = smem + 208;
    if (tid < NH) {
        sAB[tid] = 1.f - exp2f(fminf(fmaxf(la[tid], -3.32f), -0.015f));
        sBet[tid] = exp2f(fminf(fmaxf(lb[tid], -2.f), 2.f));
        sEma[tid] = ema0[tid];
    }

    if (blockIdx.x < 32) {  // ======== CHAIN ========
        const int pair = blockIdx.x, b = pair >> 4, h = pair & 15;
        {
            const float* Mg = g_M + (size_t)pair * CS * CS;
            float* buf = smem + HDR;
            for (int i = tid; i < 1024; i += TPB)
                cpa16(buf + CM_M + (i >> 4) * 68 + (i & 15) * 4, Mg + (i >> 4) * 64 + (i & 15) * 4);
            if (tid < CS) cpa4(buf + CM_A + tid, A + ((size_t)b * SEQ + tid) * NH + h);
        }
        CP_COMMIT();
        __syncthreads();
        for (int c = 0; c < NC; ++c) {
            float* cur = smem + HDR + ((c & 1) ? CBUF : 0);
            float* nxt = smem + HDR + ((c & 1) ? 0 : CBUF);
            if (c + 1 < NC) {
                const float* Mg = g_M + (size_t)((c + 1) * NPAIR + pair) * CS * CS;
                for (int i = tid; i < 1024; i += TPB)
                    cpa16(nxt + CM_M + (i >> 4) * 68 + (i & 15) * 4, Mg + (i >> 4) * 64 + (i & 15) * 4);
                if (tid < CS)
                    cpa4(nxt + CM_A + tid, A + ((size_t)b * SEQ + (c + 1) * CS + tid) * NH + h);
                CP_COMMIT(); CP_WAIT1();
            } else CP_WAIT0();
            __syncthreads();
            if (wid == 0) scan_warp0(lane, cur + CM_A, sP);
            if (c > 0) {
                if (tid == 0) wait_arrive(32u * (unsigned)c);
                __syncthreads();
                if (wid == 0) gate_warp0(c, lane, sEma, sAB, sBet, sDS);
            } else if (tid == 0) sDS[0] = 1.f;
            __syncthreads();
            const float dsv = sDS[0], pT = sP[CS - 1];
            if (tid < CS) sW[tid] = __expf(dsv * (pT - sP[tid]));
            if (pair == 0 && tid == 64) g_ds[c] = dsv;
            __syncthreads();
            {   // err = w^T M w  (double accumulation)
                int r = tid & 63, seg = tid >> 6;
                const float* mrow = cur + CM_M + r * 68 + seg * 16;
                const float* ws = sW + seg * 16;
                double p = 0.0;
#pragma unroll
                for (int i = 0; i < 4; i++) {
                    float4 m = *(const float4*)(mrow + i * 4);
                    float4 wv = *(const float4*)(ws + i * 4);
                    p += (double)m.x * wv.x + (double)m.y * wv.y
                       + (double)m.z * wv.z + (double)m.w * wv.w;
                }
                p *= (double)sW[r];
#pragma unroll
                for (int o = 16; o; o >>= 1) p += __shfl_xor_sync(0xffffffffu, p, o);
                if (lane == 0) sRedD[wid] = p;
            }
            __syncthreads();
            if (tid == 0) {
                double tot = 0.0;
#pragma unroll
                for (int w = 0; w < 8; w++) tot += sRedD[w];
                float totf = (float)tot;
                asm volatile("st.global.cg.f32 [%0], %1;" :: "l"(&g_err[c][pair]), "f"(totf) : "memory");
                unsigned d_;
                asm volatile("atom.release.gpu.global.add.u32 %0, [%1], 1;"
                             : "=r"(d_) : "l"(&g_arrive) : "memory");
            }
        }
    } else {  // ======== WORKER ========
        const int idx = blockIdx.x - 32;
        const int pair = idx >> 2, slice = idx & 3;
        const int b = pair >> 4, h = pair & 15;
        const int p0 = slice * 16;
        const int n0 = tid & 127, ph = (tid >> 7) * 8;
        float4 hA = make_float4(0.f, 0.f, 0.f, 0.f);
        float4 hB = make_float4(0.f, 0.f, 0.f, 0.f);
        {
            float* buf = smem + HDR;
            const float* Bg = Bm + ((size_t)b * SEQ * NH + h) * DN;
            const float* Xg = X + ((size_t)b * SEQ * NH + h) * DP + p0;
            for (int i2 = tid; i2 < 2048; i2 += TPB)
                cpa16(buf + WB_B + (i2 >> 5) * DN + (i2 & 31) * 4, Bg + (size_t)(i2 >> 5) * 2048 + (i2 & 31) * 4);
            if (tid < 256) cpa16(buf + WB_X + (tid >> 2) * 16 + (tid & 3) * 4,
                                 Xg + (size_t)(tid >> 2) * 1024 + (tid & 3) * 4);
            if (tid < CS) cpa4(buf + WB_A + tid, A + ((size_t)b * SEQ + tid) * NH + h);
        }
        CP_COMMIT();
        __syncthreads();
        for (int c = 0; c < NC; ++c) {
            float* cur = smem + HDR + ((c & 1) ? WBUF : 0);
            float* nxt = smem + HDR + ((c & 1) ? 0 : WBUF);
            if (c + 1 < NC) {
                size_t rb = ((size_t)b * SEQ + (c + 1) * CS) * NH + h;
                const float* Bg = Bm + rb * DN;
                const float* Xg = X + rb * DP + p0;
                for (int i2 = tid; i2 < 2048; i2 += TPB)
                    cpa16(nxt + WB_B + (i2 >> 5) * DN + (i2 & 31) * 4, Bg + (size_t)(i2 >> 5) * 2048 + (i2 & 31) * 4);
                if (tid < 256) cpa16(nxt + WB_X + (tid >> 2) * 16 + (tid & 3) * 4,
                                     Xg + (size_t)(tid >> 2) * 1024 + (tid & 3) * 4);
                if (tid < CS) cpa4(nxt + WB_A + tid, A + ((size_t)b * SEQ + (c + 1) * CS + tid) * NH + h);
                CP_COMMIT(); CP_WAIT1();
            } else CP_WAIT0();
            __syncthreads();
            if (wid == 0) scan_warp0(lane, cur + WB_A, sP);
            if (c > 0) {
                if (tid == 0) wait_arrive(32u * (unsigned)c);
                __syncthreads();
                if (wid == 0) gate_warp0(c, lane, sEma, sAB, sBet, sDS);
            } else if (tid == 0) sDS[0] = 1.f;
            __syncthreads();
            const float dsv = sDS[0], pT = sP[CS - 1];
#pragma unroll
            for (int k = tid; k < CS * 16; k += TPB)
                sXw[k] = __expf(dsv * (pT - sP[k >> 4])) * cur[WB_X + k];
            __syncthreads();
            {
                const float* xw = sXw + ph;
                float4 c1 = make_float4(0.f, 0.f, 0.f, 0.f);
                float4 c2 = make_float4(0.f, 0.f, 0.f, 0.f);
#pragma unroll 8
                for (int t = 0; t < CS; t++) {
                    float b1 = cur[WB_B + t * DN + n0];
                    float4 w0 = *(const float4*)(xw + t * 16);
                    float4 w1 = *(const float4*)(xw + t * 16 + 4);
                    c1.x = fmaf(b1, w0.x, c1.x); c1.y = fmaf(b1, w0.y, c1.y);
                    c1.z = fmaf(b1, w0.z, c1.z); c1.w = fmaf(b1, w0.w, c1.w);
                    c2.x = fmaf(b1, w1.x, c2.x); c2.y = fmaf(b1, w1.y, c2.y);
                    c2.z = fmaf(b1, w1.z, c2.z); c2.w = fmaf(b1, w1.w, c2.w);
                }
                float dt = __expf(dsv * pT);
                hA.x = fmaf(dt, hA.x, c1.x); hA.y = fmaf(dt, hA.y, c1.y);
                hA.z = fmaf(dt, hA.z, c1.z); hA.w = fmaf(dt, hA.w, c1.w);
                hB.x = fmaf(dt, hB.x, c2.x); hB.y = fmaf(dt, hB.y, c2.y);
                hB.z = fmaf(dt, hB.z, c2.z); hB.w = fmaf(dt, hB.w, c2.w);
            }
            if (c + 1 < NC) {
                float* gh = g_h + ((size_t)(c + 1) * NPAIR + pair) * (DN * DP)
                            + (size_t)(p0 + ph) * DN + n0;
                gh[0 * DN] = hA.x; gh[1 * DN] = hA.y; gh[2 * DN] = hA.z; gh[3 * DN] = hA.w;
                gh[4 * DN] = hB.x; gh[5 * DN] = hB.y; gh[6 * DN] = hB.z; gh[7 * DN] = hB.w;
            }
            __syncthreads();
        }
    }
}

// ---------------- PASS 2 (unchanged structure) ----------------
#define P2_C 0
#define P2_H 8192
#define P2_CB 16384
#define P2_X 20480
#define P2_A 24576
#define P2_P 24640
#define P2_DFS 24704
#define P2_INV 24768
#define SMEM2_FLOATS 24832

__global__ void __launch_bounds__(P2TPB, 2) pass2_kernel(
    const float* __restrict__ X, const float* __restrict__ A,
    const float* __restrict__ Cm, float* __restrict__ Y) {
    extern __shared__ float smem[];
    const int tid = threadIdx.x, lane = tid & 31, wid = tid >> 5;
    const int c = blockIdx.x >> 5, pair = blockIdx.x & 31;
    const int b = pair >> 4, h = pair & 15;
    const int yi = tid & 63, pq = tid >> 6;
    float* sC = smem + P2_C; float* sH = smem + P2_H; float* sCB = smem + P2_CB;
    float* sX = smem + P2_X; float* sP = smem + P2_P;
    float* sDfs = smem + P2_DFS; float* sInv = smem + P2_INV;
    const size_t rowbase = ((size_t)((size_t)b * SEQ + (size_t)c * CS) * NH + h);
    const float* Cg = Cm + rowbase * DN;
    const float* Xg = X + rowbase * DP;
    const float* CBg = g_CB + (size_t)(c * NPAIR + pair) * CS * CS;
    const float* Hg = g_h + ((size_t)c * NPAIR + pair) * (DN * DP);
#pragma unroll
    for (int idx = tid; idx < 2048; idx += P2TPB) {
        int i = idx >> 5, g = idx & 31;
        cpa16(sC + i * DN + ((g ^ (i & 31)) << 2), Cg + (size_t)i * 2048 + g * 4);
    }
    if (c > 0)
#pragma unroll
        for (int idx = tid; idx < 2048; idx += P2TPB) cpa16(sH + idx * 4, Hg + idx * 4);
#pragma unroll
    for (int idx = tid; idx < 1024; idx += P2TPB) {
        int i = idx >> 4, g4 = idx & 15;
        cpa16(sCB + i * CS + ((g4 ^ (i & 15)) << 2), CBg + i * CS + g4 * 4);
    }
#pragma unroll
    for (int idx = tid; idx < 1024; idx += P2TPB) {
        int j = idx >> 4, p4 = idx & 15;
        cpa16(sX + j * DP + p4 * 4, Xg + (size_t)j * 1024 + p4 * 4);
    }
    if (tid < CS) cpa4(smem + P2_A + tid, A + ((size_t)b * SEQ + c * CS + tid) * NH + h);
    CP_COMMIT(); CP_WAIT0();
    __syncthreads();
    if (wid == 0) scan_warp0(lane, smem + P2_A, sP);
    __syncthreads();
    const float dsv = (c == 0) ? 1.f : __ldg(&g_ds[c]);
    if (tid < CS) {
        float a = dsv * sP[tid];
        sDfs[tid] = __expf(a); sInv[tid] = __expf(-a);
    }
    __syncthreads();
#pragma unroll
    for (int idx = tid; idx < CS * DP; idx += P2TPB) sX[idx] *= sInv[idx >> 6];
#pragma unroll
    for (int idx = tid; idx < CS * CS; idx += P2TPB) {
        int i = idx >> 6, j = idx & 63;
        if (j > i) sCB[i * CS + (((j >> 2) ^ (i & 15)) << 2) + (j & 3)] = 0.f;
    }
    __syncthreads();
    float acc[8] = {};
    if (c > 0) {
        const float* crow = sC + yi * DN;
        const int sw = yi & 31;
        const float* hb = sH + pq * 8 * DN;
#pragma unroll 4
        for (int g = 0; g < 32; g++) {
            float4 cv = *(const float4*)(crow + ((g ^ sw) << 2));
#pragma unroll
            for (int e = 0; e < 8; e++) {
                float4 hv = *(const float4*)(hb + e * DN + g * 4);
                acc[e] = fmaf(cv.x, hv.x, acc[e]); acc[e] = fmaf(cv.y, hv.y, acc[e]);
                acc[e] = fmaf(cv.z, hv.z, acc[e]); acc[e] = fmaf(cv.w, hv.w, acc[e]);
            }
        }
    }
    {
        const float* cbrow = sCB + yi * CS;
        const int sw4 = yi & 15;
        const int gmax = (yi < 32) ? 8 : 16;
        for (int g4 = 0; g4 < gmax; g4++) {
            float4 cb = *(const float4*)(cbrow + ((g4 ^ sw4) << 2));
#pragma unroll
            for (int k = 0; k < 4; k++) {
                float cbk = (k == 0) ? cb.x : (k == 1) ? cb.y : (k == 2) ? cb.z : cb.w;
                const float* xr = sX + (g4 * 4 + k) * DP + pq * 8;
                float4 x0 = *(const float4*)(xr);
                float4 x1 = *(const float4*)(xr + 4);
                acc[0] = fmaf(cbk, x0.x, acc[0]); acc[1] = fmaf(cbk, x0.y, acc[1]);
                acc[2] = fmaf(cbk, x0.z, acc[2]); acc[3] = fmaf(cbk, x0.w, acc[3]);
                acc[4] = fmaf(cbk, x1.x, acc[4]); acc[5] = fmaf(cbk, x1.y, acc[5]);
                acc[6] = fmaf(cbk, x1.z, acc[6]); acc[7] = fmaf(cbk, x1.w, acc[7]);
            }
        }
    }
    {
        float d = sDfs[yi];
        float* yo = Y + (rowbase + (size_t)yi * NH) * DP + pq * 8;
        *(float4*)yo = make_float4(acc[0] * d, acc[1] * d, acc[2] * d, acc[3] * d);
        *(float4*)(yo + 4) = make_float4(acc[4] * d, acc[5] * d, acc[6] * d, acc[7] * d);
    }
}

extern "C" void kernel_launch(void* const* d_in, const int* in_sizes, int n_in,
                              void* d_out, int out_size) {
    const float* X = (const float*)d_in[0];
    const float* A = (const float*)d_in[1];
    const float* Bm = (const float*)d_in[2];
    const float* Cm = (const float*)d_in[3];
    const float* la = (const float*)d_in[4];
    const float* lb = (const float*)d_in[5];
    const float* em = (const float*)d_in[6];
    float* Y = (float*)d_out;
    const int prep_smem = (2 * 8192 + 4096) * sizeof(float);   // 81920 B
    const int p1_smem = SMEM1_FLOATS * sizeof(float);
    const int p2_smem = SMEM2_FLOATS * sizeof(float);
    cudaFuncSetAttribute(prep_kernel, cudaFuncAttributeMaxDynamicSharedMemorySize, prep_smem);
    cudaFuncSetAttribute(pass1_kernel, cudaFuncAttributeMaxDynamicSharedMemorySize, p1_smem);
    cudaFuncSetAttribute(pass2_kernel, cudaFuncAttributeMaxDynamicSharedMemorySize, p2_smem);
    prep_kernel<<<NC * NPAIR, PTPB, prep_smem>>>(Cm, Bm, X);
    pass1_kernel<<<160, TPB, p1_smem>>>(X, A, Bm, la, lb, em);
    pass2_kernel<<<NC * NPAIR, P2TPB, p2_smem>>>(X, A, Cm, Y);
}

// round 15
// speedup vs baseline: 1.3864x; 1.3850x over previous
#include <cuda_runtime.h>

#define BSZ 2
#define SEQ 4096
#define NH 16
#define DP 64
#define DN 128
#define CS 64
#define NC 64
#define NPAIR 32
#define P1NC 63            // chunk 63 h/err are dead
#define P1_CTAS 128
#define P1TPB 512
#define PTPB 512
#define P2TPB 512

__device__ float g_CB[(size_t)NC * NPAIR * CS * CS];
__device__ float g_h[(size_t)NC * NPAIR * DN * DP];
__device__ float g_err[NC][NPAIR];
__device__ unsigned g_dsp[NC];     // ds for chunk c as float bits; 0 = not ready
__device__ float g_ema[NH];
__device__ unsigned g_arrive;

__device__ __forceinline__ void cpa16(float* s, const float* g) {
    unsigned a = (unsigned)__cvta_generic_to_shared(s);
    asm volatile("cp.async.cg.shared.global [%0], [%1], 16;\n" :: "r"(a), "l"(g));
}
__device__ __forceinline__ void cpa4(float* s, const float* g) {
    unsigned a = (unsigned)__cvta_generic_to_shared(s);
    asm volatile("cp.async.ca.shared.global [%0], [%1], 4;\n" :: "r"(a), "l"(g));
}
#define CP_COMMIT() asm volatile("cp.async.commit_group;\n" ::: "memory")
#define CP_WAIT1()  asm volatile("cp.async.wait_group 1;\n" ::: "memory")
#define CP_WAIT0()  asm volatile("cp.async.wait_group 0;\n" ::: "memory")

__device__ __forceinline__ float dot4(float4 a, float4 b) {
    return fmaf(a.x, b.x, fmaf(a.y, b.y, fmaf(a.z, b.z, a.w * b.w)));
}

__device__ __forceinline__ void scan_warp0(int lane, const float* sA, float* sP) {
    float v0 = sA[2 * lane], v1 = sA[2 * lane + 1];
    float s = v0 + v1;
#pragma unroll
    for (int o = 1; o < 32; o <<= 1) {
        float t = __shfl_up_sync(0xffffffffu, s, o);
        if (lane >= o) s += t;
    }
    sP[2 * lane] = s - v1;
    sP[2 * lane + 1] = s;
}

// ============================================================================
// CB kernel: CB = C·B^T via conflict-free warp-strip (rows broadcast, cols/lane)
// Also resets all cross-kernel sync state for this replay.
// ============================================================================
__global__ void __launch_bounds__(PTPB, 1) cb_kernel(const float* __restrict__ Cm,
                                                     const float* __restrict__ Bm) {
    const int tid = threadIdx.x;
    if (blockIdx.x == 0) {     // reset sync state (kernel boundary orders vs pass1)
        if (tid == 0) g_arrive = 0u;
        for (int i = tid; i < NC * NPAIR; i += PTPB) ((float*)g_err)[i] = 0.f;
        for (int i = tid; i < NC; i += PTPB) g_dsp[i] = 0u;
    }
    extern __shared__ float smem[];
    float* sC = smem;          // [64][128] XOR-swizzled float4 groups
    float* sB = smem + 8192;
    const int c = blockIdx.x >> 5, pair = blockIdx.x & 31;
    const int b = pair >> 4, h = pair & 15;
    const size_t rb = ((size_t)((size_t)b * SEQ + (size_t)c * CS) * NH + h);
    const float* Cg = Cm + rb * DN;
    const float* Bg = Bm + rb * DN;
    for (int idx = tid; idx < 2048; idx += PTPB) {
        int i = idx >> 5, g = idx & 31;
        cpa16(sC + i * 128 + ((g ^ (i & 31)) << 2), Cg + (size_t)i * 2048 + g * 4);
        cpa16(sB + i * 128 + ((g ^ (i & 31)) << 2), Bg + (size_t)i * 2048 + g * 4);
    }
    CP_COMMIT(); CP_WAIT0();
    __syncthreads();

    const int w = tid >> 5, l = tid & 31;
    const int r0 = w * 4;
    const int j1 = l, j2 = l + 32;
    const bool hi = (w >= 8);            // rows >= 32 need cols 32..63 too
    const float4* sC4 = (const float4*)sC;
    const float4* sB4 = (const float4*)sB;
    float cb1[4] = {}, cb2[4] = {};
#pragma unroll 4
    for (int k4 = 0; k4 < 32; k4++) {
        float4 bj1 = sB4[j1 * 32 + (k4 ^ j1)];
        float4 bj2 = hi ? sB4[j2 * 32 + (k4 ^ (j2 & 31))] : make_float4(0.f, 0.f, 0.f, 0.f);
#pragma unroll
        for (int a = 0; a < 4; a++) {
            int rr = r0 + a;
            float4 cr = sC4[rr * 32 + (k4 ^ (rr & 31))];
            cb1[a] += dot4(cr, bj1);
            if (hi) cb2[a] += dot4(cr, bj2);
        }
    }
    float* cbo = g_CB + (size_t)(c * NPAIR + pair) * CS * CS;
#pragma unroll
    for (int a = 0; a < 4; a++) {
        cbo[(r0 + a) * CS + j1] = cb1[a];
        if (hi) cbo[(r0 + a) * CS + j2] = cb2[a];
    }
}

// ============================================================================
// PASS 1: 128 CTAs (pair x 4 p-slices of 16), direct err + elected gate
// ============================================================================
// header floats: sP 0..63 | sDS 64 | sRed 68..83 | sXw 96..1119
#define HDR 1120
#define WB_B 0             // B [64][128]
#define WB_X 8192          // X slice [64][16]
#define WB_A 9216          // 64
#define WBUF 9280
#define SMEM1_FLOATS (HDR + 2 * WBUF)   // 19680 floats = 78720 B

__device__ __forceinline__ void p1_prefetch(
    int cc, float* buf, int b, int h, int p0, int tid,
    const float* __restrict__ X, const float* __restrict__ A,
    const float* __restrict__ Bm) {
    size_t rb = ((size_t)((size_t)b * SEQ + (size_t)cc * CS) * NH + h);
    const float* Bg = Bm + rb * DN;
    const float* Xg = X + rb * DP + p0;
#pragma unroll
    for (int i2 = tid; i2 < 2048; i2 += P1TPB)
        cpa16(buf + WB_B + (i2 >> 5) * DN + (i2 & 31) * 4,
              Bg + (size_t)(i2 >> 5) * 2048 + (i2 & 31) * 4);
    if (tid < 256)
        cpa16(buf + WB_X + (tid >> 2) * 16 + (tid & 3) * 4,
              Xg + (size_t)(tid >> 2) * 1024 + (tid & 3) * 4);
    if (tid < CS)
        cpa4(buf + WB_A + tid, A + ((size_t)b * SEQ + (size_t)cc * CS + tid) * NH + h);
}

__global__ void __launch_bounds__(P1TPB, 1) pass1_kernel(
    const float* __restrict__ X, const float* __restrict__ A,
    const float* __restrict__ Bm,
    const float* __restrict__ la, const float* __restrict__ lb,
    const float* __restrict__ ema0) {
    extern __shared__ float smem[];
    const int tid = threadIdx.x, lane = tid & 31, wid = tid >> 5;
    const int pair = blockIdx.x >> 2, slice = blockIdx.x & 3;
    const int b = pair >> 4, h = pair & 15;
    const int p0 = slice * 16;
    const int n0 = tid & 127, pl = (tid >> 7) * 4;
    float* sP = smem; float* sDS = smem + 64; float* sRed = smem + 68;
    float* sXw = smem + 96;
    float4 hreg = make_float4(0.f, 0.f, 0.f, 0.f);

    p1_prefetch(0, smem + HDR, b, h, p0, tid, X, A, Bm);
    CP_COMMIT();
    __syncthreads();

    for (int c = 0; c < P1NC; ++c) {
        float* cur = smem + HDR + ((c & 1) ? WBUF : 0);
        float* nxt = smem + HDR + ((c & 1) ? 0 : WBUF);
        if (c + 1 < P1NC) {
            p1_prefetch(c + 1, nxt, b, h, p0, tid, X, A, Bm);
            CP_COMMIT(); CP_WAIT1();
        } else CP_WAIT0();
        __syncthreads();

        if (wid == 0) scan_warp0(lane, cur + WB_A, sP);

        // ---- obtain ds_c ----
        if (c == 0) {
            if (tid == 0) sDS[0] = 1.f;
        } else if (tid == 0) {
            unsigned v;
            do {
                asm volatile("ld.acquire.gpu.global.u32 %0, [%1];"
                             : "=r"(v) : "l"(&g_dsp[c]) : "memory");
            } while (v == 0u);
            sDS[0] = __uint_as_float(v);
        }
        __syncthreads();

        const float dsv = sDS[0], pT = sP[CS - 1];
#pragma unroll
        for (int k = tid; k < CS * 16; k += P1TPB)
            sXw[k] = __expf(dsv * (pT - sP[k >> 4])) * cur[WB_X + k];
        __syncthreads();

        // ---- h = dt*h + B^T @ (dte*X); err partial ----
        float esum;
        {
            const float* xw = sXw + pl;
            float4 c1 = make_float4(0.f, 0.f, 0.f, 0.f);
#pragma unroll 8
            for (int t = 0; t < CS; t++) {
                float b1 = cur[WB_B + t * DN + n0];
                float4 w = *(const float4*)(xw + t * 16);
                c1.x = fmaf(b1, w.x, c1.x); c1.y = fmaf(b1, w.y, c1.y);
                c1.z = fmaf(b1, w.z, c1.z); c1.w = fmaf(b1, w.w, c1.w);
            }
            float dt = __expf(dsv * pT);
            hreg.x = fmaf(dt, hreg.x, c1.x); hreg.y = fmaf(dt, hreg.y, c1.y);
            hreg.z = fmaf(dt, hreg.z, c1.z); hreg.w = fmaf(dt, hreg.w, c1.w);
            esum = c1.x * c1.x + c1.y * c1.y + c1.z * c1.z + c1.w * c1.w;
        }
        // store h_prev for chunk c+1 (p-major)
        {
            float* gh = g_h + ((size_t)(c + 1) * NPAIR + pair) * (DN * DP)
                        + (size_t)(p0 + pl) * DN + n0;
            gh[0] = hreg.x; gh[DN] = hreg.y; gh[2 * DN] = hreg.z; gh[3 * DN] = hreg.w;
        }
#pragma unroll
        for (int o = 16; o; o >>= 1) esum += __shfl_xor_sync(0xffffffffu, esum, o);
        if (lane == 0) sRed[wid] = esum;
        __syncthreads();

        // ---- warp0 tail: publish err, arrive, elected computes gate ----
        if (wid == 0) {
            bool elected = false;
            if (lane == 0) {
                float tot = 0.f;
#pragma unroll
                for (int w2 = 0; w2 < 16; w2++) tot += sRed[w2];
                asm volatile("red.global.add.f32 [%0], %1;"
                             :: "l"(&g_err[c][pair]), "f"(tot) : "memory");
                unsigned old;
                asm volatile("atom.acq_rel.gpu.global.add.u32 %0, [%1], 1;"
                             : "=r"(old) : "l"(&g_arrive) : "memory");
                elected = (old == (unsigned)P1_CTAS * (unsigned)(c + 1) - 1u);
            }
            elected = __shfl_sync(0xffffffffu, (int)elected, 0);
            if (elected) {
                // gate for ds_{c+1}; lane = pair index
                int hh = lane & 15;
                float e = __ldcg(&g_err[c][lane]) * (1.f / 8192.f);
                float e0 = __shfl_sync(0xffffffffu, e, hh);
                float e1 = __shfl_sync(0xffffffffu, e, hh + 16);
                float ema_prev = (c == 0) ? ema0[hh] : __ldcg(&g_ema[hh]);
                float emn = 0.99f * ema_prev + 0.01f * (0.5f * (e0 + e1));
                if (lane < 16) {
                    asm volatile("st.global.cg.f32 [%0], %1;"
                                 :: "l"(&g_ema[hh]), "f"(emn) : "memory");
                }
                float nrm = e / (emn + 1e-6f);
                float bet = exp2f(fminf(fmaxf(lb[hh], -2.f), 2.f));
                float ab = 1.f - exp2f(fminf(fmaxf(la[hh], -3.32f), -0.015f));
                float boost = fmaxf(tanhf(bet * nrm), 0.f);
                float alpha = fminf(fmaxf(ab + (1.f - ab) * boost, 0.01f), 0.999f);
                float oma = 1.f - alpha;
#pragma unroll
                for (int o = 16; o; o >>= 1) oma += __shfl_xor_sync(0xffffffffu, oma, o);
                if (lane == 0) {
                    unsigned bits = __float_as_uint(oma * (1.f / 32.f));
                    asm volatile("st.release.gpu.global.u32 [%0], %1;"
                                 :: "l"(&g_dsp[c + 1]), "r"(bits) : "memory");
                }
            }
        }
        // no trailing syncthreads: next iteration's post-poll sync re-converges;
        // buffers/sXw/sP are only rewritten after that sync.
    }
}

// ---------------- PASS 2: Y = dfs_i * ( (L∘CB) @ X + C @ h_prev ) ----------------
#define P2_C 0
#define P2_H 8192
#define P2_CB 16384
#define P2_X 20480
#define P2_A 24576
#define P2_P 24640
#define P2_DFS 24704
#define P2_INV 24768
#define SMEM2_FLOATS 24832

__global__ void __launch_bounds__(P2TPB, 2) pass2_kernel(
    const float* __restrict__ X, const float* __restrict__ A,
    const float* __restrict__ Cm, float* __restrict__ Y) {
    extern __shared__ float smem[];
    const int tid = threadIdx.x, lane = tid & 31, wid = tid >> 5;
    const int c = blockIdx.x >> 5, pair = blockIdx.x & 31;
    const int b = pair >> 4, h = pair & 15;
    const int yi = tid & 63, pq = tid >> 6;
    float* sC = smem + P2_C; float* sH = smem + P2_H; float* sCB = smem + P2_CB;
    float* sX = smem + P2_X; float* sP = smem + P2_P;
    float* sDfs = smem + P2_DFS; float* sInv = smem + P2_INV;
    const size_t rowbase = ((size_t)((size_t)b * SEQ + (size_t)c * CS) * NH + h);
    const float* Cg = Cm + rowbase * DN;
    const float* Xg = X + rowbase * DP;
    const float* CBg = g_CB + (size_t)(c * NPAIR + pair) * CS * CS;
    const float* Hg = g_h + ((size_t)c * NPAIR + pair) * (DN * DP);
#pragma unroll
    for (int idx = tid; idx < 2048; idx += P2TPB) {
        int i = idx >> 5, g = idx & 31;
        cpa16(sC + i * DN + ((g ^ (i & 31)) << 2), Cg + (size_t)i * 2048 + g * 4);
    }
    if (c > 0)
#pragma unroll
        for (int idx = tid; idx < 2048; idx += P2TPB) cpa16(sH + idx * 4, Hg + idx * 4);
#pragma unroll
    for (int idx = tid; idx < 1024; idx += P2TPB) {
        int i = idx >> 4, g4 = idx & 15;
        cpa16(sCB + i * CS + ((g4 ^ (i & 15)) << 2), CBg + i * CS + g4 * 4);
    }
#pragma unroll
    for (int idx = tid; idx < 1024; idx += P2TPB) {
        int j = idx >> 4, p4 = idx & 15;
        cpa16(sX + j * DP + p4 * 4, Xg + (size_t)j * 1024 + p4 * 4);
    }
    if (tid < CS) cpa4(smem + P2_A + tid, A + ((size_t)b * SEQ + c * CS + tid) * NH + h);
    CP_COMMIT(); CP_WAIT0();
    __syncthreads();
    if (wid == 0) scan_warp0(lane, smem + P2_A, sP);
    __syncthreads();
    const float dsv = (c == 0) ? 1.f
                               : __uint_as_float(__ldg((const unsigned*)&g_dsp[c]));
    if (tid < CS) {
        float a = dsv * sP[tid];
        sDfs[tid] = __expf(a); sInv[tid] = __expf(-a);
    }
    __syncthreads();
#pragma unroll
    for (int idx = tid; idx < CS * DP; idx += P2TPB) sX[idx] *= sInv[idx >> 6];
#pragma unroll
    for (int idx = tid; idx < CS * CS; idx += P2TPB) {
        int i = idx >> 6, j = idx & 63;
        if (j > i) sCB[i * CS + (((j >> 2) ^ (i & 15)) << 2) + (j & 3)] = 0.f;
    }
    __syncthreads();
    float acc[8] = {};
    if (c > 0) {
        const float* crow = sC + yi * DN;
        const int sw = yi & 31;
        const float* hb = sH + pq * 8 * DN;
#pragma unroll 4
        for (int g = 0; g < 32; g++) {
            float4 cv = *(const float4*)(crow + ((g ^ sw) << 2));
#pragma unroll
            for (int e = 0; e < 8; e++) {
                float4 hv = *(const float4*)(hb + e * DN + g * 4);
                acc[e] = fmaf(cv.x, hv.x, acc[e]); acc[e] = fmaf(cv.y, hv.y, acc[e]);
                acc[e] = fmaf(cv.z, hv.z, acc[e]); acc[e] = fmaf(cv.w, hv.w, acc[e]);
            }
        }
    }
    {
        const float* cbrow = sCB + yi * CS;
        const int sw4 = yi & 15;
        const int gmax = (yi < 32) ? 8 : 16;
        for (int g4 = 0; g4 < gmax; g4++) {
            float4 cb = *(const float4*)(cbrow + ((g4 ^ sw4) << 2));
#pragma unroll
            for (int k = 0; k < 4; k++) {
                float cbk = (k == 0) ? cb.x : (k == 1) ? cb.y : (k == 2) ? cb.z : cb.w;
                const float* xr = sX + (g4 * 4 + k) * DP + pq * 8;
                float4 x0 = *(const float4*)(xr);
                float4 x1 = *(const float4*)(xr + 4);
                acc[0] = fmaf(cbk, x0.x, acc[0]); acc[1] = fmaf(cbk, x0.y, acc[1]);
                acc[2] = fmaf(cbk, x0.z, acc[2]); acc[3] = fmaf(cbk, x0.w, acc[3]);
                acc[4] = fmaf(cbk, x1.x, acc[4]); acc[5] = fmaf(cbk, x1.y, acc[5]);
                acc[6] = fmaf(cbk, x1.z, acc[6]); acc[7] = fmaf(cbk, x1.w, acc[7]);
            }
        }
    }
    {
        float d = sDfs[yi];
        float* yo = Y + (rowbase + (size_t)yi * NH) * DP + pq * 8;
        *(float4*)yo = make_float4(acc[0] * d, acc[1] * d, acc[2] * d, acc[3] * d);
        *(float4*)(yo + 4) = make_float4(acc[4] * d, acc[5] * d, acc[6] * d, acc[7] * d);
    }
}

extern "C" void kernel_launch(void* const* d_in, const int* in_sizes, int n_in,
                              void* d_out, int out_size) {
    const float* X = (const float*)d_in[0];
    const float* A = (const float*)d_in[1];
    const float* Bm = (const float*)d_in[2];
    const float* Cm = (const float*)d_in[3];
    const float* la = (const float*)d_in[4];
    const float* lb = (const float*)d_in[5];
    const float* em = (const float*)d_in[6];
    float* Y = (float*)d_out;
    const int cb_smem = 2 * 8192 * sizeof(float);            // 64 KB
    const int p1_smem = SMEM1_FLOATS * sizeof(float);        // ~79 KB
    const int p2_smem = SMEM2_FLOATS * sizeof(float);        // ~99 KB
    cudaFuncSetAttribute(cb_kernel, cudaFuncAttributeMaxDynamicSharedMemorySize, cb_smem);
    cudaFuncSetAttribute(pass1_kernel, cudaFuncAttributeMaxDynamicSharedMemorySize, p1_smem);
    cudaFuncSetAttribute(pass2_kernel, cudaFuncAttributeMaxDynamicSharedMemorySize, p2_smem);
    cb_kernel<<<NC * NPAIR, PTPB, cb_smem>>>(Cm, Bm);
    pass1_kernel<<<P1_CTAS, P1TPB, p1_smem>>>(X, A, Bm, la, lb, em);
    pass2_kernel<<<NC * NPAIR, P2TPB, p2_smem>>>(X, A, Cm, Y);
}